// round 13
// baseline (speedup 1.0000x reference)
#include <cuda_runtime.h>
#include <cuda_bf16.h>
#include <math.h>
#include <stdint.h>

#define NNODES 100000
#define NEDGES 1600000
#define INDIM  128
#define HID    64
#define OUTDIM 10

// ---------------------------------------------------------------------------
// Device-global scratch. g_deg is zero at load and re-zeroed by k_scan1 each
// call, so every call does identical work on identical state.
// ---------------------------------------------------------------------------
__device__ float g_dis[NNODES];
__device__ float g_A[(size_t)NNODES * HID];   // xw = X @ W (raw, no dis)
__device__ float g_C[(size_t)NNODES * HID];   // h  = post-relu activations
__device__ int   g_deg[NNODES];               // stays zeroed between calls
__device__ int   g_rowptr[NNODES + 1];        // BLOCK-LOCAL exclusive prefix
__device__ int   g_cursor[NNODES];            // block-local cursors
__device__ int   g_csr[NEDGES];               // source node per CSR slot
__device__ int   g_bsum[128];                 // exclusive scan of block totals

__device__ __forceinline__ uint32_t smem_u32(const void* p) {
    uint32_t a;
    asm("{ .reg .u64 t; cvta.to.shared.u64 t, %1; cvt.u32.u64 %0, t; }"
        : "=r"(a) : "l"(p));
    return a;
}

__device__ __forceinline__ void ldsm_x4(uint32_t* r, uint32_t addr) {
    asm volatile("ldmatrix.sync.aligned.m8n8.x4.shared.b16 {%0,%1,%2,%3}, [%4];"
                 : "=r"(r[0]), "=r"(r[1]), "=r"(r[2]), "=r"(r[3]) : "r"(addr));
}

__device__ __forceinline__ void mma_bf16(float* c, const uint32_t* a,
                                         uint32_t b0, uint32_t b1) {
    asm volatile(
        "mma.sync.aligned.m16n8k16.row.col.f32.bf16.bf16.f32 "
        "{%0,%1,%2,%3}, {%4,%5,%6,%7}, {%8,%9}, {%0,%1,%2,%3};"
        : "+f"(c[0]), "+f"(c[1]), "+f"(c[2]), "+f"(c[3])
        : "r"(a[0]), "r"(a[1]), "r"(a[2]), "r"(a[3]), "r"(b0), "r"(b1));
}

// ---------------------------------------------------------------------------
// CSR build
// ---------------------------------------------------------------------------
__global__ void k_deg(const int* __restrict__ col, int E) {
    int e = blockIdx.x * blockDim.x + threadIdx.x;
    if (e < E) atomicAdd(&g_deg[col[e]], 1);
}

__global__ __launch_bounds__(1024) void k_scan1(int N) {
    __shared__ int s[1024];
    int i = blockIdx.x * 1024 + threadIdx.x;
    int v = 0;
    if (i < N) {
        v = g_deg[i];
        g_deg[i] = 0;                          // restore invariant
        g_dis[i] = rsqrtf((float)(v + 1));     // +1 self loop
    }
    s[threadIdx.x] = v;
    __syncthreads();
#pragma unroll
    for (int off = 1; off < 1024; off <<= 1) {
        int t = (threadIdx.x >= off) ? s[threadIdx.x - off] : 0;
        __syncthreads();
        s[threadIdx.x] += t;
        __syncthreads();
    }
    if (i < N) {
        int ex = s[threadIdx.x] - v;
        g_rowptr[i] = ex;
        g_cursor[i] = ex;
    }
    if (i == N - 1) g_rowptr[N] = s[threadIdx.x];
    if (threadIdx.x == 1023) g_bsum[blockIdx.x] = s[1023];
}

__global__ __launch_bounds__(128) void k_scan2(int nb) {
    __shared__ int s[128];
    int t = threadIdx.x;
    int v = (t < nb) ? g_bsum[t] : 0;
    s[t] = v;
    __syncthreads();
#pragma unroll
    for (int off = 1; off < 128; off <<= 1) {
        int u = (t >= off) ? s[t - off] : 0;
        __syncthreads();
        s[t] += u;
        __syncthreads();
    }
    if (t < nb) g_bsum[t] = s[t] - v;
}

__global__ void k_fill(const int* __restrict__ row,
                       const int* __restrict__ col, int E) {
    int e = blockIdx.x * blockDim.x + threadIdx.x;
    if (e < E) {
        int c = col[e];
        int p = atomicAdd(&g_cursor[c], 1) + g_bsum[c >> 10];
        g_csr[p] = row[e];
    }
}

// ---------------------------------------------------------------------------
// Tensor-core GEMM via mma.sync: g_A[node] = X[node] @ W  (no dis scaling;
// dis is applied in the gather so this kernel has no CSR dependency).
// 128-node tile x 64 outs; split-bf16 D = Ah@Bh + Al@Bh + Ah@Bl (~2^-16 err).
// Warp w: nodes [w*16, w*16+16) x all 64 outs.
// Per k16-step: 2x ldmatrix.x4 (A hi/lo) + 8x ldmatrix.x4 (B hi/lo, two n8
// blocks per load) + 24 HMMA.16816.
// Rows padded to K*2+16 bytes (rows differ by 16 mod 128 -> conflict-free).
// ---------------------------------------------------------------------------
template <int K, bool USE_G_C>
__global__ __launch_bounds__(256) void k_gemm_mma(const float* __restrict__ X,
                                                  const float* __restrict__ W,
                                                  int N) {
    extern __shared__ char smem[];
    constexpr int STRIDE = K * 2 + 16;           // padded row bytes
    constexpr int ASZ = 128 * STRIDE;
    constexpr int BSZ = 64 * STRIDE;
    constexpr int OFF_AH = 0;
    constexpr int OFF_AL = ASZ;
    constexpr int OFF_BH = 2 * ASZ;
    constexpr int OFF_BL = 2 * ASZ + BSZ;

    const float* __restrict__ Xp = USE_G_C ? (const float*)g_C : X;
    const int tid = threadIdx.x;
    const int w = tid >> 5;
    const int lane = tid & 31;
    const int nodeBase = blockIdx.x * 128;

    // ---- convert X tile -> bf16 hi/lo ----
#pragma unroll
    for (int t = 0; t < K / 8; t++) {
        int idx = tid + 256 * t;
        int nl = idx / (K / 4);
        int f4 = idx % (K / 4);
        int node = nodeBase + nl;
        float4 v = make_float4(0.f, 0.f, 0.f, 0.f);
        if (node < N) v = ((const float4*)(Xp + (size_t)node * K))[f4];
        __nv_bfloat16 h0 = __float2bfloat16_rn(v.x);
        __nv_bfloat16 h1 = __float2bfloat16_rn(v.y);
        __nv_bfloat16 h2 = __float2bfloat16_rn(v.z);
        __nv_bfloat16 h3 = __float2bfloat16_rn(v.w);
        __nv_bfloat16 l0 = __float2bfloat16_rn(v.x - __bfloat162float(h0));
        __nv_bfloat16 l1 = __float2bfloat16_rn(v.y - __bfloat162float(h1));
        __nv_bfloat16 l2 = __float2bfloat16_rn(v.z - __bfloat162float(h2));
        __nv_bfloat16 l3 = __float2bfloat16_rn(v.w - __bfloat162float(h3));
        uint32_t hA = (uint32_t)__bfloat16_as_ushort(h0) |
                      ((uint32_t)__bfloat16_as_ushort(h1) << 16);
        uint32_t hB = (uint32_t)__bfloat16_as_ushort(h2) |
                      ((uint32_t)__bfloat16_as_ushort(h3) << 16);
        uint32_t lA = (uint32_t)__bfloat16_as_ushort(l0) |
                      ((uint32_t)__bfloat16_as_ushort(l1) << 16);
        uint32_t lB = (uint32_t)__bfloat16_as_ushort(l2) |
                      ((uint32_t)__bfloat16_as_ushort(l3) << 16);
        int off = nl * STRIDE + f4 * 8;
        *(uint32_t*)(smem + OFF_AH + off) = hA;
        *(uint32_t*)(smem + OFF_AH + off + 4) = hB;
        *(uint32_t*)(smem + OFF_AL + off) = lA;
        *(uint32_t*)(smem + OFF_AL + off + 4) = lB;
    }

    // ---- convert W -> B = W^T, bf16 hi/lo (scalar transpose) ----
#pragma unroll
    for (int t = 0; t < K / 4; t++) {
        int idx = tid + 256 * t;
        int n = idx & 63;
        int k = idx >> 6;
        float wv = W[(size_t)k * 64 + n];
        __nv_bfloat16 h = __float2bfloat16_rn(wv);
        __nv_bfloat16 l = __float2bfloat16_rn(wv - __bfloat162float(h));
        int off = n * STRIDE + k * 2;
        *(unsigned short*)(smem + OFF_BH + off) = __bfloat16_as_ushort(h);
        *(unsigned short*)(smem + OFF_BL + off) = __bfloat16_as_ushort(l);
    }
    __syncthreads();

    const uint32_t sb = smem_u32(smem);
    const uint32_t aRow = w * 16 + (lane & 15);
    const uint32_t aAdd = aRow * STRIDE + ((lane >> 4) << 4);
    // B x4 addressing: lanes 0-7/8-15 -> n8 block (jp*2) k0-7/k8-15;
    // lanes 16-23/24-31 -> n8 block (jp*2+1).
    const uint32_t bRowBase = ((lane >> 4) << 3) + (lane & 7);
    const uint32_t bKsel = (((lane >> 3) & 1) << 4);

    float acc[8][4];
#pragma unroll
    for (int j = 0; j < 8; j++)
#pragma unroll
        for (int r = 0; r < 4; r++) acc[j][r] = 0.0f;

#pragma unroll
    for (int s = 0; s < K / 16; s++) {
        uint32_t cb = s * 32;
        uint32_t ah[4], al[4];
        ldsm_x4(ah, sb + OFF_AH + aAdd + cb);
        ldsm_x4(al, sb + OFF_AL + aAdd + cb);
#pragma unroll
        for (int jp = 0; jp < 4; jp++) {
            uint32_t badd = (jp * 16 + bRowBase) * STRIDE + bKsel + cb;
            uint32_t bh[4], bl[4];
            ldsm_x4(bh, sb + OFF_BH + badd);
            ldsm_x4(bl, sb + OFF_BL + badd);
            mma_bf16(acc[jp * 2 + 0], ah, bh[0], bh[1]);
            mma_bf16(acc[jp * 2 + 0], al, bh[0], bh[1]);
            mma_bf16(acc[jp * 2 + 0], ah, bl[0], bl[1]);
            mma_bf16(acc[jp * 2 + 1], ah, bh[2], bh[3]);
            mma_bf16(acc[jp * 2 + 1], al, bh[2], bh[3]);
            mma_bf16(acc[jp * 2 + 1], ah, bl[2], bl[3]);
        }
    }

    // ---- epilogue: store raw XW (dis applied later in gather) ----
    int g = lane >> 2, tq = lane & 3;
    int n0 = nodeBase + w * 16 + g;
    int n1 = n0 + 8;
    if (n0 < N) {
        float* dst = g_A + (size_t)n0 * HID + tq * 2;
#pragma unroll
        for (int j = 0; j < 8; j++)
            *(float2*)(dst + j * 8) = make_float2(acc[j][0], acc[j][1]);
    }
    if (n1 < N) {
        float* dst = g_A + (size_t)n1 * HID + tq * 2;
#pragma unroll
        for (int j = 0; j < 8; j++)
            *(float2*)(dst + j * 8) = make_float2(acc[j][2], acc[j][3]);
    }
}

// ---------------------------------------------------------------------------
// Gather + epilogue with dis applied here:
//   g_C[c] = relu(dis[c] * (dis[c]*xw[c] + sum_r dis[r]*xw[r]) + b)
// One warp per node; lane owns 2 consecutive floats.
// ---------------------------------------------------------------------------
__global__ __launch_bounds__(256) void k_gather(const float* __restrict__ b,
                                                int N) {
    int w = (blockIdx.x * 256 + threadIdx.x) >> 5;
    if (w >= N) return;
    int lane = threadIdx.x & 31;

    const float2* __restrict__ A2 = (const float2*)g_A;
    float dw = g_dis[w];
    float2 s0 = A2[(size_t)w * 32 + lane];   // self-loop term (x dis[w])
    float2 a0 = make_float2(s0.x * dw, s0.y * dw);
    float2 a1 = make_float2(0.f, 0.f);
    float2 a2 = make_float2(0.f, 0.f);
    float2 a3 = make_float2(0.f, 0.f);

    int beg = g_rowptr[w] + g_bsum[w >> 10];
    int end = g_rowptr[w + 1] + g_bsum[(w + 1) >> 10];

    for (int i = beg; i < end; i += 32) {
        int n = end - i;
        if (n > 32) n = 32;
        int idx = (lane < n) ? g_csr[i + lane] : 0;
        int j = 0;
        for (; j + 3 < n; j += 4) {
            int r0 = __shfl_sync(0xffffffffu, idx, j);
            int r1 = __shfl_sync(0xffffffffu, idx, j + 1);
            int r2 = __shfl_sync(0xffffffffu, idx, j + 2);
            int r3 = __shfl_sync(0xffffffffu, idx, j + 3);
            float dr0 = g_dis[r0];
            float dr1 = g_dis[r1];
            float dr2 = g_dis[r2];
            float dr3 = g_dis[r3];
            float2 v0 = A2[(size_t)r0 * 32 + lane];
            float2 v1 = A2[(size_t)r1 * 32 + lane];
            float2 v2 = A2[(size_t)r2 * 32 + lane];
            float2 v3 = A2[(size_t)r3 * 32 + lane];
            a0.x = fmaf(v0.x, dr0, a0.x); a0.y = fmaf(v0.y, dr0, a0.y);
            a1.x = fmaf(v1.x, dr1, a1.x); a1.y = fmaf(v1.y, dr1, a1.y);
            a2.x = fmaf(v2.x, dr2, a2.x); a2.y = fmaf(v2.y, dr2, a2.y);
            a3.x = fmaf(v3.x, dr3, a3.x); a3.y = fmaf(v3.y, dr3, a3.y);
        }
        for (; j < n; j++) {
            int r = __shfl_sync(0xffffffffu, idx, j);
            float dr = g_dis[r];
            float2 v = A2[(size_t)r * 32 + lane];
            a0.x = fmaf(v.x, dr, a0.x);
            a0.y = fmaf(v.y, dr, a0.y);
        }
    }

    float sx = a0.x + a1.x + a2.x + a3.x;
    float sy = a0.y + a1.y + a2.y + a3.y;
    float2 bb = ((const float2*)b)[lane];
    float ox = dw * sx + bb.x;
    float oy = dw * sy + bb.y;
    float2 o;
    o.x = ox > 0.f ? ox : 0.f;
    o.y = oy > 0.f ? oy : 0.f;
    ((float2*)g_C)[(size_t)w * 32 + lane] = o;
}

// ---------------------------------------------------------------------------
// Head: out = log_softmax(g_C @ Wl + bl). One thread per node.
// ---------------------------------------------------------------------------
__global__ __launch_bounds__(128) void k_head(const float* __restrict__ Wl,
                                              const float* __restrict__ bl,
                                              float* __restrict__ out, int N) {
    __shared__ float Ws[HID * OUTDIM];
    __shared__ float Bs[OUTDIM];
    int tid = threadIdx.x;
    for (int i = tid; i < HID * OUTDIM; i += 128) Ws[i] = Wl[i];
    if (tid < OUTDIM) Bs[tid] = bl[tid];
    __syncthreads();

    int node = blockIdx.x * 128 + tid;
    if (node >= N) return;

    float acc[OUTDIM];
#pragma unroll
    for (int o = 0; o < OUTDIM; o++) acc[o] = Bs[o];

    const float4* h4 = (const float4*)(g_C + (size_t)node * HID);
#pragma unroll
    for (int c4 = 0; c4 < 16; c4++) {
        float4 v = h4[c4];
#pragma unroll
        for (int o = 0; o < OUTDIM; o++) {
            acc[o] = fmaf(v.x, Ws[(c4 * 4 + 0) * OUTDIM + o], acc[o]);
            acc[o] = fmaf(v.y, Ws[(c4 * 4 + 1) * OUTDIM + o], acc[o]);
            acc[o] = fmaf(v.z, Ws[(c4 * 4 + 2) * OUTDIM + o], acc[o]);
            acc[o] = fmaf(v.w, Ws[(c4 * 4 + 3) * OUTDIM + o], acc[o]);
        }
    }

    float m = acc[0];
#pragma unroll
    for (int o = 1; o < OUTDIM; o++) m = fmaxf(m, acc[o]);
    float s = 0.0f;
#pragma unroll
    for (int o = 0; o < OUTDIM; o++) s += expf(acc[o] - m);
    float lse = m + logf(s);
#pragma unroll
    for (int o = 0; o < OUTDIM; o++)
        out[(size_t)node * OUTDIM + o] = acc[o] - lse;
}

// ---------------------------------------------------------------------------
extern "C" void kernel_launch(void* const* d_in, const int* in_sizes, int n_in,
                              void* d_out, int out_size) {
    const float* x = (const float*)d_in[0];
    const int* ei = (const int*)d_in[1];   // int64 in reference -> int32 here
    const float* W1 = (const float*)d_in[2];
    const float* b1 = (const float*)d_in[3];
    const float* W2 = (const float*)d_in[4];
    const float* b2 = (const float*)d_in[5];
    const float* Wl = (const float*)d_in[6];
    const float* bl = (const float*)d_in[7];
    float* out = (float*)d_out;

    int N = in_sizes[0] / INDIM;
    int E = in_sizes[1] / 2;
    const int* row = ei;
    const int* col = ei + E;

    int nbE = (E + 255) / 256;
    int nbScan = (N + 1023) / 1024;

    constexpr int S1 = INDIM * 2 + 16;
    constexpr int S2 = HID * 2 + 16;
    constexpr int SMEM1 = 2 * (128 * S1) + 2 * (64 * S1);   // ~104.5 KB
    constexpr int SMEM2 = 2 * (128 * S2) + 2 * (64 * S2);   // ~55.3 KB
    cudaFuncSetAttribute(k_gemm_mma<INDIM, false>,
                         cudaFuncAttributeMaxDynamicSharedMemorySize, SMEM1);
    cudaFuncSetAttribute(k_gemm_mma<HID, true>,
                         cudaFuncAttributeMaxDynamicSharedMemorySize, SMEM2);

    // Side stream + events, created once (host-side only; identical GPU work
    // on every call, so graph capture and replay see the same DAG).
    static cudaStream_t s2 = nullptr;
    static cudaEvent_t evFork = nullptr, evCSR = nullptr;
    if (s2 == nullptr) {
        cudaStreamCreateWithFlags(&s2, cudaStreamNonBlocking);
        cudaEventCreateWithFlags(&evFork, cudaEventDisableTiming);
        cudaEventCreateWithFlags(&evCSR, cudaEventDisableTiming);
    }

    // Fork: CSR build chain on s2, concurrent with layer-1 GEMM (which no
    // longer depends on dis).
    cudaEventRecord(evFork, 0);
    cudaStreamWaitEvent(s2, evFork, 0);
    k_deg<<<nbE, 256, 0, s2>>>(col, E);
    k_scan1<<<nbScan, 1024, 0, s2>>>(N);
    k_scan2<<<1, 128, 0, s2>>>(nbScan);
    k_fill<<<nbE, 256, 0, s2>>>(row, col, E);
    cudaEventRecord(evCSR, s2);

    // Layer 1 GEMM on main stream, overlapping the CSR chain.
    k_gemm_mma<INDIM, false><<<(N + 127) / 128, 256, SMEM1>>>(x, W1, N);

    // Join: gather needs both g_A (main) and CSR + dis (s2).
    cudaStreamWaitEvent(0, evCSR, 0);
    k_gather<<<(N * 32 + 255) / 256, 256>>>(b1, N);

    // Layer 2
    k_gemm_mma<HID, true><<<(N + 127) / 128, 256, SMEM2>>>(x, W2, N);
    k_gather<<<(N * 32 + 255) / 256, 256>>>(b2, N);

    // Head + log_softmax
    k_head<<<(N + 127) / 128, 128>>>(Wl, bl, out, N);
}

// round 15
// speedup vs baseline: 1.0032x; 1.0032x over previous
#include <cuda_runtime.h>
#include <cuda_bf16.h>
#include <math.h>
#include <stdint.h>

#define NNODES 100000
#define NEDGES 1600000
#define INDIM  128
#define HID    64
#define OUTDIM 10

// ---------------------------------------------------------------------------
// Device-global scratch. g_deg is zero at load and re-zeroed by k_scan1 each
// call, so every call does identical work on identical state.
// ---------------------------------------------------------------------------
__device__ float g_dis[NNODES];
__device__ float g_A[(size_t)NNODES * HID];   // xw = X @ W (raw, no dis)
__device__ float g_C[(size_t)NNODES * HID];   // h  = post-relu activations
__device__ int   g_deg[NNODES];               // stays zeroed between calls
__device__ int   g_rowptr[NNODES + 1];        // BLOCK-LOCAL exclusive prefix
__device__ int   g_cursor[NNODES];            // block-local cursors
__device__ int   g_csr[NEDGES];               // source node per CSR slot
__device__ int   g_bsum[128];                 // exclusive scan of block totals

__device__ __forceinline__ uint32_t smem_u32(const void* p) {
    uint32_t a;
    asm("{ .reg .u64 t; cvta.to.shared.u64 t, %1; cvt.u32.u64 %0, t; }"
        : "=r"(a) : "l"(p));
    return a;
}

__device__ __forceinline__ void ldsm_x4(uint32_t* r, uint32_t addr) {
    asm volatile("ldmatrix.sync.aligned.m8n8.x4.shared.b16 {%0,%1,%2,%3}, [%4];"
                 : "=r"(r[0]), "=r"(r[1]), "=r"(r[2]), "=r"(r[3]) : "r"(addr));
}

__device__ __forceinline__ void mma_bf16(float* c, const uint32_t* a,
                                         uint32_t b0, uint32_t b1) {
    asm volatile(
        "mma.sync.aligned.m16n8k16.row.col.f32.bf16.bf16.f32 "
        "{%0,%1,%2,%3}, {%4,%5,%6,%7}, {%8,%9}, {%0,%1,%2,%3};"
        : "+f"(c[0]), "+f"(c[1]), "+f"(c[2]), "+f"(c[3])
        : "r"(a[0]), "r"(a[1]), "r"(a[2]), "r"(a[3]), "r"(b0), "r"(b1));
}

// ---------------------------------------------------------------------------
// CSR build
// ---------------------------------------------------------------------------
__global__ void k_deg(const int* __restrict__ col, int E) {
    int e = blockIdx.x * blockDim.x + threadIdx.x;
    if (e < E) atomicAdd(&g_deg[col[e]], 1);
}

__global__ __launch_bounds__(1024) void k_scan1(int N) {
    __shared__ int s[1024];
    int i = blockIdx.x * 1024 + threadIdx.x;
    int v = 0;
    if (i < N) {
        v = g_deg[i];
        g_deg[i] = 0;                          // restore invariant
        g_dis[i] = rsqrtf((float)(v + 1));     // +1 self loop
    }
    s[threadIdx.x] = v;
    __syncthreads();
#pragma unroll
    for (int off = 1; off < 1024; off <<= 1) {
        int t = (threadIdx.x >= off) ? s[threadIdx.x - off] : 0;
        __syncthreads();
        s[threadIdx.x] += t;
        __syncthreads();
    }
    if (i < N) {
        int ex = s[threadIdx.x] - v;
        g_rowptr[i] = ex;
        g_cursor[i] = ex;
    }
    if (i == N - 1) g_rowptr[N] = s[threadIdx.x];
    if (threadIdx.x == 1023) g_bsum[blockIdx.x] = s[1023];
}

__global__ __launch_bounds__(128) void k_scan2(int nb) {
    __shared__ int s[128];
    int t = threadIdx.x;
    int v = (t < nb) ? g_bsum[t] : 0;
    s[t] = v;
    __syncthreads();
#pragma unroll
    for (int off = 1; off < 128; off <<= 1) {
        int u = (t >= off) ? s[t - off] : 0;
        __syncthreads();
        s[t] += u;
        __syncthreads();
    }
    if (t < nb) g_bsum[t] = s[t] - v;
}

__global__ void k_fill(const int* __restrict__ row,
                       const int* __restrict__ col, int E) {
    int e = blockIdx.x * blockDim.x + threadIdx.x;
    if (e < E) {
        int c = col[e];
        int p = atomicAdd(&g_cursor[c], 1) + g_bsum[c >> 10];
        g_csr[p] = row[e];
    }
}

// ---------------------------------------------------------------------------
// Tensor-core GEMM via mma.sync: g_A[node] = X[node] @ W  (no dis scaling;
// dis is applied in the gather so this kernel has no CSR dependency).
// 128-node tile x 64 outs; split-bf16 D = Ah@Bh + Al@Bh + Ah@Bl (~2^-16 err).
// Warp w: nodes [w*16, w*16+16) x all 64 outs.
// Per k16-step: 2x ldmatrix.x4 (A hi/lo) + 8x ldmatrix.x4 (B hi/lo, two n8
// blocks per load) + 24 HMMA.16816.
// Rows padded to K*2+16 bytes (rows differ by 16 mod 128 -> conflict-free).
// ---------------------------------------------------------------------------
template <int K, bool USE_G_C>
__global__ __launch_bounds__(256) void k_gemm_mma(const float* __restrict__ X,
                                                  const float* __restrict__ W,
                                                  int N) {
    extern __shared__ char smem[];
    constexpr int STRIDE = K * 2 + 16;           // padded row bytes
    constexpr int ASZ = 128 * STRIDE;
    constexpr int BSZ = 64 * STRIDE;
    constexpr int OFF_AH = 0;
    constexpr int OFF_AL = ASZ;
    constexpr int OFF_BH = 2 * ASZ;
    constexpr int OFF_BL = 2 * ASZ + BSZ;

    const float* __restrict__ Xp = USE_G_C ? (const float*)g_C : X;
    const int tid = threadIdx.x;
    const int w = tid >> 5;
    const int lane = tid & 31;
    const int nodeBase = blockIdx.x * 128;

    // ---- convert X tile -> bf16 hi/lo ----
#pragma unroll
    for (int t = 0; t < K / 8; t++) {
        int idx = tid + 256 * t;
        int nl = idx / (K / 4);
        int f4 = idx % (K / 4);
        int node = nodeBase + nl;
        float4 v = make_float4(0.f, 0.f, 0.f, 0.f);
        if (node < N) v = ((const float4*)(Xp + (size_t)node * K))[f4];
        __nv_bfloat16 h0 = __float2bfloat16_rn(v.x);
        __nv_bfloat16 h1 = __float2bfloat16_rn(v.y);
        __nv_bfloat16 h2 = __float2bfloat16_rn(v.z);
        __nv_bfloat16 h3 = __float2bfloat16_rn(v.w);
        __nv_bfloat16 l0 = __float2bfloat16_rn(v.x - __bfloat162float(h0));
        __nv_bfloat16 l1 = __float2bfloat16_rn(v.y - __bfloat162float(h1));
        __nv_bfloat16 l2 = __float2bfloat16_rn(v.z - __bfloat162float(h2));
        __nv_bfloat16 l3 = __float2bfloat16_rn(v.w - __bfloat162float(h3));
        uint32_t hA = (uint32_t)__bfloat16_as_ushort(h0) |
                      ((uint32_t)__bfloat16_as_ushort(h1) << 16);
        uint32_t hB = (uint32_t)__bfloat16_as_ushort(h2) |
                      ((uint32_t)__bfloat16_as_ushort(h3) << 16);
        uint32_t lA = (uint32_t)__bfloat16_as_ushort(l0) |
                      ((uint32_t)__bfloat16_as_ushort(l1) << 16);
        uint32_t lB = (uint32_t)__bfloat16_as_ushort(l2) |
                      ((uint32_t)__bfloat16_as_ushort(l3) << 16);
        int off = nl * STRIDE + f4 * 8;
        *(uint32_t*)(smem + OFF_AH + off) = hA;
        *(uint32_t*)(smem + OFF_AH + off + 4) = hB;
        *(uint32_t*)(smem + OFF_AL + off) = lA;
        *(uint32_t*)(smem + OFF_AL + off + 4) = lB;
    }

    // ---- convert W -> B = W^T, bf16 hi/lo (scalar transpose) ----
#pragma unroll
    for (int t = 0; t < K / 4; t++) {
        int idx = tid + 256 * t;
        int n = idx & 63;
        int k = idx >> 6;
        float wv = W[(size_t)k * 64 + n];
        __nv_bfloat16 h = __float2bfloat16_rn(wv);
        __nv_bfloat16 l = __float2bfloat16_rn(wv - __bfloat162float(h));
        int off = n * STRIDE + k * 2;
        *(unsigned short*)(smem + OFF_BH + off) = __bfloat16_as_ushort(h);
        *(unsigned short*)(smem + OFF_BL + off) = __bfloat16_as_ushort(l);
    }
    __syncthreads();

    const uint32_t sb = smem_u32(smem);
    const uint32_t aRow = w * 16 + (lane & 15);
    const uint32_t aAdd = aRow * STRIDE + ((lane >> 4) << 4);
    // B x4 addressing: lanes 0-7/8-15 -> n8 block (jp*2) k0-7/k8-15;
    // lanes 16-23/24-31 -> n8 block (jp*2+1).
    const uint32_t bRowBase = ((lane >> 4) << 3) + (lane & 7);
    const uint32_t bKsel = (((lane >> 3) & 1) << 4);

    float acc[8][4];
#pragma unroll
    for (int j = 0; j < 8; j++)
#pragma unroll
        for (int r = 0; r < 4; r++) acc[j][r] = 0.0f;

#pragma unroll
    for (int s = 0; s < K / 16; s++) {
        uint32_t cb = s * 32;
        uint32_t ah[4], al[4];
        ldsm_x4(ah, sb + OFF_AH + aAdd + cb);
        ldsm_x4(al, sb + OFF_AL + aAdd + cb);
#pragma unroll
        for (int jp = 0; jp < 4; jp++) {
            uint32_t badd = (jp * 16 + bRowBase) * STRIDE + bKsel + cb;
            uint32_t bh[4], bl[4];
            ldsm_x4(bh, sb + OFF_BH + badd);
            ldsm_x4(bl, sb + OFF_BL + badd);
            mma_bf16(acc[jp * 2 + 0], ah, bh[0], bh[1]);
            mma_bf16(acc[jp * 2 + 0], al, bh[0], bh[1]);
            mma_bf16(acc[jp * 2 + 0], ah, bl[0], bl[1]);
            mma_bf16(acc[jp * 2 + 1], ah, bh[2], bh[3]);
            mma_bf16(acc[jp * 2 + 1], al, bh[2], bh[3]);
            mma_bf16(acc[jp * 2 + 1], ah, bl[2], bl[3]);
        }
    }

    // ---- epilogue: store raw XW (dis applied later in gather) ----
    int g = lane >> 2, tq = lane & 3;
    int n0 = nodeBase + w * 16 + g;
    int n1 = n0 + 8;
    if (n0 < N) {
        float* dst = g_A + (size_t)n0 * HID + tq * 2;
#pragma unroll
        for (int j = 0; j < 8; j++)
            *(float2*)(dst + j * 8) = make_float2(acc[j][0], acc[j][1]);
    }
    if (n1 < N) {
        float* dst = g_A + (size_t)n1 * HID + tq * 2;
#pragma unroll
        for (int j = 0; j < 8; j++)
            *(float2*)(dst + j * 8) = make_float2(acc[j][2], acc[j][3]);
    }
}

// ---------------------------------------------------------------------------
// Gather + epilogue with dis applied here:
//   g_C[c] = relu(dis[c] * (dis[c]*xw[c] + sum_r dis[r]*xw[r]) + b)
// One warp per node; lane owns 2 consecutive floats.
// ---------------------------------------------------------------------------
__global__ __launch_bounds__(256) void k_gather(const float* __restrict__ b,
                                                int N) {
    int w = (blockIdx.x * 256 + threadIdx.x) >> 5;
    if (w >= N) return;
    int lane = threadIdx.x & 31;

    const float2* __restrict__ A2 = (const float2*)g_A;
    float dw = g_dis[w];
    float2 s0 = A2[(size_t)w * 32 + lane];   // self-loop term (x dis[w])
    float2 a0 = make_float2(s0.x * dw, s0.y * dw);
    float2 a1 = make_float2(0.f, 0.f);
    float2 a2 = make_float2(0.f, 0.f);
    float2 a3 = make_float2(0.f, 0.f);

    int beg = g_rowptr[w] + g_bsum[w >> 10];
    int end = g_rowptr[w + 1] + g_bsum[(w + 1) >> 10];

    for (int i = beg; i < end; i += 32) {
        int n = end - i;
        if (n > 32) n = 32;
        int idx = (lane < n) ? g_csr[i + lane] : 0;
        int j = 0;
        for (; j + 3 < n; j += 4) {
            int r0 = __shfl_sync(0xffffffffu, idx, j);
            int r1 = __shfl_sync(0xffffffffu, idx, j + 1);
            int r2 = __shfl_sync(0xffffffffu, idx, j + 2);
            int r3 = __shfl_sync(0xffffffffu, idx, j + 3);
            float dr0 = g_dis[r0];
            float dr1 = g_dis[r1];
            float dr2 = g_dis[r2];
            float dr3 = g_dis[r3];
            float2 v0 = A2[(size_t)r0 * 32 + lane];
            float2 v1 = A2[(size_t)r1 * 32 + lane];
            float2 v2 = A2[(size_t)r2 * 32 + lane];
            float2 v3 = A2[(size_t)r3 * 32 + lane];
            a0.x = fmaf(v0.x, dr0, a0.x); a0.y = fmaf(v0.y, dr0, a0.y);
            a1.x = fmaf(v1.x, dr1, a1.x); a1.y = fmaf(v1.y, dr1, a1.y);
            a2.x = fmaf(v2.x, dr2, a2.x); a2.y = fmaf(v2.y, dr2, a2.y);
            a3.x = fmaf(v3.x, dr3, a3.x); a3.y = fmaf(v3.y, dr3, a3.y);
        }
        for (; j < n; j++) {
            int r = __shfl_sync(0xffffffffu, idx, j);
            float dr = g_dis[r];
            float2 v = A2[(size_t)r * 32 + lane];
            a0.x = fmaf(v.x, dr, a0.x);
            a0.y = fmaf(v.y, dr, a0.y);
        }
    }

    float sx = a0.x + a1.x + a2.x + a3.x;
    float sy = a0.y + a1.y + a2.y + a3.y;
    float2 bb = ((const float2*)b)[lane];
    float ox = dw * sx + bb.x;
    float oy = dw * sy + bb.y;
    float2 o;
    o.x = ox > 0.f ? ox : 0.f;
    o.y = oy > 0.f ? oy : 0.f;
    ((float2*)g_C)[(size_t)w * 32 + lane] = o;
}

// ---------------------------------------------------------------------------
// Head: out = log_softmax(g_C @ Wl + bl). One thread per node.
// ---------------------------------------------------------------------------
__global__ __launch_bounds__(128) void k_head(const float* __restrict__ Wl,
                                              const float* __restrict__ bl,
                                              float* __restrict__ out, int N) {
    __shared__ float Ws[HID * OUTDIM];
    __shared__ float Bs[OUTDIM];
    int tid = threadIdx.x;
    for (int i = tid; i < HID * OUTDIM; i += 128) Ws[i] = Wl[i];
    if (tid < OUTDIM) Bs[tid] = bl[tid];
    __syncthreads();

    int node = blockIdx.x * 128 + tid;
    if (node >= N) return;

    float acc[OUTDIM];
#pragma unroll
    for (int o = 0; o < OUTDIM; o++) acc[o] = Bs[o];

    const float4* h4 = (const float4*)(g_C + (size_t)node * HID);
#pragma unroll
    for (int c4 = 0; c4 < 16; c4++) {
        float4 v = h4[c4];
#pragma unroll
        for (int o = 0; o < OUTDIM; o++) {
            acc[o] = fmaf(v.x, Ws[(c4 * 4 + 0) * OUTDIM + o], acc[o]);
            acc[o] = fmaf(v.y, Ws[(c4 * 4 + 1) * OUTDIM + o], acc[o]);
            acc[o] = fmaf(v.z, Ws[(c4 * 4 + 2) * OUTDIM + o], acc[o]);
            acc[o] = fmaf(v.w, Ws[(c4 * 4 + 3) * OUTDIM + o], acc[o]);
        }
    }

    float m = acc[0];
#pragma unroll
    for (int o = 1; o < OUTDIM; o++) m = fmaxf(m, acc[o]);
    float s = 0.0f;
#pragma unroll
    for (int o = 0; o < OUTDIM; o++) s += expf(acc[o] - m);
    float lse = m + logf(s);
#pragma unroll
    for (int o = 0; o < OUTDIM; o++)
        out[(size_t)node * OUTDIM + o] = acc[o] - lse;
}

// ---------------------------------------------------------------------------
extern "C" void kernel_launch(void* const* d_in, const int* in_sizes, int n_in,
                              void* d_out, int out_size) {
    const float* x = (const float*)d_in[0];
    const int* ei = (const int*)d_in[1];   // int64 in reference -> int32 here
    const float* W1 = (const float*)d_in[2];
    const float* b1 = (const float*)d_in[3];
    const float* W2 = (const float*)d_in[4];
    const float* b2 = (const float*)d_in[5];
    const float* Wl = (const float*)d_in[6];
    const float* bl = (const float*)d_in[7];
    float* out = (float*)d_out;

    int N = in_sizes[0] / INDIM;
    int E = in_sizes[1] / 2;
    const int* row = ei;
    const int* col = ei + E;

    int nbE = (E + 255) / 256;
    int nbScan = (N + 1023) / 1024;

    constexpr int S1 = INDIM * 2 + 16;
    constexpr int S2 = HID * 2 + 16;
    constexpr int SMEM1 = 2 * (128 * S1) + 2 * (64 * S1);   // ~104.5 KB
    constexpr int SMEM2 = 2 * (128 * S2) + 2 * (64 * S2);   // ~55.3 KB
    cudaFuncSetAttribute(k_gemm_mma<INDIM, false>,
                         cudaFuncAttributeMaxDynamicSharedMemorySize, SMEM1);
    cudaFuncSetAttribute(k_gemm_mma<HID, true>,
                         cudaFuncAttributeMaxDynamicSharedMemorySize, SMEM2);

    // Side stream + events, created once (host-side only; identical GPU work
    // on every call, so graph capture and replay see the same DAG).
    static cudaStream_t s2 = nullptr;
    static cudaEvent_t evFork = nullptr, evCSR = nullptr;
    if (s2 == nullptr) {
        cudaStreamCreateWithFlags(&s2, cudaStreamNonBlocking);
        cudaEventCreateWithFlags(&evFork, cudaEventDisableTiming);
        cudaEventCreateWithFlags(&evCSR, cudaEventDisableTiming);
    }

    // Fork: CSR build chain on s2, concurrent with layer-1 GEMM (which no
    // longer depends on dis).
    cudaEventRecord(evFork, 0);
    cudaStreamWaitEvent(s2, evFork, 0);
    k_deg<<<nbE, 256, 0, s2>>>(col, E);
    k_scan1<<<nbScan, 1024, 0, s2>>>(N);
    k_scan2<<<1, 128, 0, s2>>>(nbScan);
    k_fill<<<nbE, 256, 0, s2>>>(row, col, E);
    cudaEventRecord(evCSR, s2);

    // Layer 1 GEMM on main stream, overlapping the CSR chain.
    k_gemm_mma<INDIM, false><<<(N + 127) / 128, 256, SMEM1>>>(x, W1, N);

    // Join: gather needs both g_A (main) and CSR + dis (s2).
    cudaStreamWaitEvent(0, evCSR, 0);
    k_gather<<<(N * 32 + 255) / 256, 256>>>(b1, N);

    // Layer 2
    k_gemm_mma<HID, true><<<(N + 127) / 128, 256, SMEM2>>>(x, W2, N);
    k_gather<<<(N * 32 + 255) / 256, 256>>>(b2, N);

    // Head + log_softmax
    k_head<<<(N + 127) / 128, 128>>>(Wl, bl, out, N);
}

// round 16
// speedup vs baseline: 1.1277x; 1.1242x over previous
#include <cuda_runtime.h>
#include <cuda_bf16.h>
#include <cuda_fp16.h>
#include <math.h>
#include <stdint.h>

#define NNODES 100000
#define NEDGES 1600000
#define INDIM  128
#define HID    64
#define OUTDIM 10

// ---------------------------------------------------------------------------
// Device-global scratch. g_deg is zero at load and re-zeroed by k_scan1 each
// call, so every call does identical work on identical state.
// ---------------------------------------------------------------------------
__device__ float  g_dis[NNODES];
__device__ __half g_Ah[(size_t)NNODES * HID]; // xs = dis*(X@W), fp16
__device__ float  g_C[(size_t)NNODES * HID];  // h  = post-relu activations
__device__ int    g_deg[NNODES];              // stays zeroed between calls
__device__ int    g_rowptr[NNODES + 1];       // BLOCK-LOCAL exclusive prefix
__device__ int    g_cursor[NNODES];           // block-local cursors
__device__ int    g_csr[NEDGES];              // source node per CSR slot
__device__ int    g_bsum[128];                // exclusive scan of block totals

__device__ __forceinline__ uint32_t smem_u32(const void* p) {
    uint32_t a;
    asm("{ .reg .u64 t; cvta.to.shared.u64 t, %1; cvt.u32.u64 %0, t; }"
        : "=r"(a) : "l"(p));
    return a;
}

__device__ __forceinline__ void ldsm_x4(uint32_t* r, uint32_t addr) {
    asm volatile("ldmatrix.sync.aligned.m8n8.x4.shared.b16 {%0,%1,%2,%3}, [%4];"
                 : "=r"(r[0]), "=r"(r[1]), "=r"(r[2]), "=r"(r[3]) : "r"(addr));
}

__device__ __forceinline__ void mma_bf16(float* c, const uint32_t* a,
                                         uint32_t b0, uint32_t b1) {
    asm volatile(
        "mma.sync.aligned.m16n8k16.row.col.f32.bf16.bf16.f32 "
        "{%0,%1,%2,%3}, {%4,%5,%6,%7}, {%8,%9}, {%0,%1,%2,%3};"
        : "+f"(c[0]), "+f"(c[1]), "+f"(c[2]), "+f"(c[3])
        : "r"(a[0]), "r"(a[1]), "r"(a[2]), "r"(a[3]), "r"(b0), "r"(b1));
}

// ---------------------------------------------------------------------------
// CSR build
// ---------------------------------------------------------------------------
__global__ void k_deg(const int* __restrict__ col, int E) {
    int e = blockIdx.x * blockDim.x + threadIdx.x;
    if (e < E) atomicAdd(&g_deg[col[e]], 1);
}

__global__ __launch_bounds__(1024) void k_scan1(int N) {
    __shared__ int s[1024];
    int i = blockIdx.x * 1024 + threadIdx.x;
    int v = 0;
    if (i < N) {
        v = g_deg[i];
        g_deg[i] = 0;                          // restore invariant
        g_dis[i] = rsqrtf((float)(v + 1));     // +1 self loop
    }
    s[threadIdx.x] = v;
    __syncthreads();
#pragma unroll
    for (int off = 1; off < 1024; off <<= 1) {
        int t = (threadIdx.x >= off) ? s[threadIdx.x - off] : 0;
        __syncthreads();
        s[threadIdx.x] += t;
        __syncthreads();
    }
    if (i < N) {
        int ex = s[threadIdx.x] - v;
        g_rowptr[i] = ex;
        g_cursor[i] = ex;
    }
    if (i == N - 1) g_rowptr[N] = s[threadIdx.x];
    if (threadIdx.x == 1023) g_bsum[blockIdx.x] = s[1023];
}

__global__ __launch_bounds__(128) void k_scan2(int nb) {
    __shared__ int s[128];
    int t = threadIdx.x;
    int v = (t < nb) ? g_bsum[t] : 0;
    s[t] = v;
    __syncthreads();
#pragma unroll
    for (int off = 1; off < 128; off <<= 1) {
        int u = (t >= off) ? s[t - off] : 0;
        __syncthreads();
        s[t] += u;
        __syncthreads();
    }
    if (t < nb) g_bsum[t] = s[t] - v;
}

__global__ void k_fill(const int* __restrict__ row,
                       const int* __restrict__ col, int E) {
    int e = blockIdx.x * blockDim.x + threadIdx.x;
    if (e < E) {
        int c = col[e];
        int p = atomicAdd(&g_cursor[c], 1) + g_bsum[c >> 10];
        g_csr[p] = row[e];
    }
}

// ---------------------------------------------------------------------------
// Tensor-core GEMM via mma.sync: g_Ah[node] = fp16(dis[node] * (X[node] @ W))
// 128-node tile x 64 outs; split-bf16 D = Ah@Bh + Al@Bh + Ah@Bl (~2^-16 err).
// Warp w: nodes [w*16, w*16+16) x all 64 outs.
// Per k16-step: 2x ldmatrix.x4 (A hi/lo) + 8x ldmatrix.x4 (B hi/lo, two n8
// blocks per load) + 24 HMMA.16816.
// Rows padded to K*2+16 bytes (rows differ by 16 mod 128 -> conflict-free).
// ---------------------------------------------------------------------------
template <int K, bool USE_G_C>
__global__ __launch_bounds__(256) void k_gemm_mma(const float* __restrict__ X,
                                                  const float* __restrict__ W,
                                                  int N) {
    extern __shared__ char smem[];
    constexpr int STRIDE = K * 2 + 16;           // padded row bytes
    constexpr int ASZ = 128 * STRIDE;
    constexpr int BSZ = 64 * STRIDE;
    constexpr int OFF_AH = 0;
    constexpr int OFF_AL = ASZ;
    constexpr int OFF_BH = 2 * ASZ;
    constexpr int OFF_BL = 2 * ASZ + BSZ;

    const float* __restrict__ Xp = USE_G_C ? (const float*)g_C : X;
    const int tid = threadIdx.x;
    const int w = tid >> 5;
    const int lane = tid & 31;
    const int nodeBase = blockIdx.x * 128;

    // ---- convert X tile -> bf16 hi/lo ----
#pragma unroll
    for (int t = 0; t < K / 8; t++) {
        int idx = tid + 256 * t;
        int nl = idx / (K / 4);
        int f4 = idx % (K / 4);
        int node = nodeBase + nl;
        float4 v = make_float4(0.f, 0.f, 0.f, 0.f);
        if (node < N) v = ((const float4*)(Xp + (size_t)node * K))[f4];
        __nv_bfloat16 h0 = __float2bfloat16_rn(v.x);
        __nv_bfloat16 h1 = __float2bfloat16_rn(v.y);
        __nv_bfloat16 h2 = __float2bfloat16_rn(v.z);
        __nv_bfloat16 h3 = __float2bfloat16_rn(v.w);
        __nv_bfloat16 l0 = __float2bfloat16_rn(v.x - __bfloat162float(h0));
        __nv_bfloat16 l1 = __float2bfloat16_rn(v.y - __bfloat162float(h1));
        __nv_bfloat16 l2 = __float2bfloat16_rn(v.z - __bfloat162float(h2));
        __nv_bfloat16 l3 = __float2bfloat16_rn(v.w - __bfloat162float(h3));
        uint32_t hA = (uint32_t)__bfloat16_as_ushort(h0) |
                      ((uint32_t)__bfloat16_as_ushort(h1) << 16);
        uint32_t hB = (uint32_t)__bfloat16_as_ushort(h2) |
                      ((uint32_t)__bfloat16_as_ushort(h3) << 16);
        uint32_t lA = (uint32_t)__bfloat16_as_ushort(l0) |
                      ((uint32_t)__bfloat16_as_ushort(l1) << 16);
        uint32_t lB = (uint32_t)__bfloat16_as_ushort(l2) |
                      ((uint32_t)__bfloat16_as_ushort(l3) << 16);
        int off = nl * STRIDE + f4 * 8;
        *(uint32_t*)(smem + OFF_AH + off) = hA;
        *(uint32_t*)(smem + OFF_AH + off + 4) = hB;
        *(uint32_t*)(smem + OFF_AL + off) = lA;
        *(uint32_t*)(smem + OFF_AL + off + 4) = lB;
    }

    // ---- convert W -> B = W^T, bf16 hi/lo (scalar transpose) ----
#pragma unroll
    for (int t = 0; t < K / 4; t++) {
        int idx = tid + 256 * t;
        int n = idx & 63;
        int k = idx >> 6;
        float wv = W[(size_t)k * 64 + n];
        __nv_bfloat16 h = __float2bfloat16_rn(wv);
        __nv_bfloat16 l = __float2bfloat16_rn(wv - __bfloat162float(h));
        int off = n * STRIDE + k * 2;
        *(unsigned short*)(smem + OFF_BH + off) = __bfloat16_as_ushort(h);
        *(unsigned short*)(smem + OFF_BL + off) = __bfloat16_as_ushort(l);
    }
    __syncthreads();

    const uint32_t sb = smem_u32(smem);
    const uint32_t aRow = w * 16 + (lane & 15);
    const uint32_t aAdd = aRow * STRIDE + ((lane >> 4) << 4);
    const uint32_t bRowBase = ((lane >> 4) << 3) + (lane & 7);
    const uint32_t bKsel = (((lane >> 3) & 1) << 4);

    float acc[8][4];
#pragma unroll
    for (int j = 0; j < 8; j++)
#pragma unroll
        for (int r = 0; r < 4; r++) acc[j][r] = 0.0f;

#pragma unroll
    for (int s = 0; s < K / 16; s++) {
        uint32_t cb = s * 32;
        uint32_t ah[4], al[4];
        ldsm_x4(ah, sb + OFF_AH + aAdd + cb);
        ldsm_x4(al, sb + OFF_AL + aAdd + cb);
#pragma unroll
        for (int jp = 0; jp < 4; jp++) {
            uint32_t badd = (jp * 16 + bRowBase) * STRIDE + bKsel + cb;
            uint32_t bh[4], bl[4];
            ldsm_x4(bh, sb + OFF_BH + badd);
            ldsm_x4(bl, sb + OFF_BL + badd);
            mma_bf16(acc[jp * 2 + 0], ah, bh[0], bh[1]);
            mma_bf16(acc[jp * 2 + 0], al, bh[0], bh[1]);
            mma_bf16(acc[jp * 2 + 0], ah, bl[0], bl[1]);
            mma_bf16(acc[jp * 2 + 1], ah, bh[2], bh[3]);
            mma_bf16(acc[jp * 2 + 1], al, bh[2], bh[3]);
            mma_bf16(acc[jp * 2 + 1], ah, bl[2], bl[3]);
        }
    }

    // ---- epilogue: scale by dis, convert to fp16, store ----
    int g = lane >> 2, tq = lane & 3;
    int n0 = nodeBase + w * 16 + g;
    int n1 = n0 + 8;
    float d0 = (n0 < N) ? g_dis[n0] : 0.0f;
    float d1 = (n1 < N) ? g_dis[n1] : 0.0f;
    if (n0 < N) {
        __half2* dst = (__half2*)(g_Ah + (size_t)n0 * HID) + tq;
#pragma unroll
        for (int j = 0; j < 8; j++)
            dst[j * 4] = __floats2half2_rn(acc[j][0] * d0, acc[j][1] * d0);
    }
    if (n1 < N) {
        __half2* dst = (__half2*)(g_Ah + (size_t)n1 * HID) + tq;
#pragma unroll
        for (int j = 0; j < 8; j++)
            dst[j * 4] = __floats2half2_rn(acc[j][2] * d1, acc[j][3] * d1);
    }
}

// ---------------------------------------------------------------------------
// Gather + epilogue: g_C[c] = relu(dis[c] * (xs[c] + sum_{r in N(c)} xs[r]) + b)
// xs = g_Ah (fp16, half traffic). One warp per node; lane owns 2 cols.
// ---------------------------------------------------------------------------
__global__ __launch_bounds__(256) void k_gather(const float* __restrict__ b,
                                                int N) {
    int w = (blockIdx.x * 256 + threadIdx.x) >> 5;
    if (w >= N) return;
    int lane = threadIdx.x & 31;

    const __half2* __restrict__ A2 = (const __half2*)g_Ah;
    float2 a0 = __half22float2(A2[(size_t)w * 32 + lane]);  // self-loop
    float2 a1 = make_float2(0.f, 0.f);
    float2 a2 = make_float2(0.f, 0.f);
    float2 a3 = make_float2(0.f, 0.f);

    int beg = g_rowptr[w] + g_bsum[w >> 10];
    int end = g_rowptr[w + 1] + g_bsum[(w + 1) >> 10];

    for (int i = beg; i < end; i += 32) {
        int n = end - i;
        if (n > 32) n = 32;
        int idx = (lane < n) ? g_csr[i + lane] : 0;
        int j = 0;
        for (; j + 3 < n; j += 4) {
            int r0 = __shfl_sync(0xffffffffu, idx, j);
            int r1 = __shfl_sync(0xffffffffu, idx, j + 1);
            int r2 = __shfl_sync(0xffffffffu, idx, j + 2);
            int r3 = __shfl_sync(0xffffffffu, idx, j + 3);
            float2 v0 = __half22float2(A2[(size_t)r0 * 32 + lane]);
            float2 v1 = __half22float2(A2[(size_t)r1 * 32 + lane]);
            float2 v2 = __half22float2(A2[(size_t)r2 * 32 + lane]);
            float2 v3 = __half22float2(A2[(size_t)r3 * 32 + lane]);
            a0.x += v0.x; a0.y += v0.y;
            a1.x += v1.x; a1.y += v1.y;
            a2.x += v2.x; a2.y += v2.y;
            a3.x += v3.x; a3.y += v3.y;
        }
        for (; j < n; j++) {
            int r = __shfl_sync(0xffffffffu, idx, j);
            float2 v = __half22float2(A2[(size_t)r * 32 + lane]);
            a0.x += v.x; a0.y += v.y;
        }
    }

    float sx = a0.x + a1.x + a2.x + a3.x;
    float sy = a0.y + a1.y + a2.y + a3.y;
    float d = g_dis[w];
    float2 bb = ((const float2*)b)[lane];
    float ox = d * sx + bb.x;
    float oy = d * sy + bb.y;
    float2 o;
    o.x = ox > 0.f ? ox : 0.f;
    o.y = oy > 0.f ? oy : 0.f;
    ((float2*)g_C)[(size_t)w * 32 + lane] = o;
}

// ---------------------------------------------------------------------------
// Head: out = log_softmax(g_C @ Wl + bl). One thread per node.
// ---------------------------------------------------------------------------
__global__ __launch_bounds__(128) void k_head(const float* __restrict__ Wl,
                                              const float* __restrict__ bl,
                                              float* __restrict__ out, int N) {
    __shared__ float Ws[HID * OUTDIM];
    __shared__ float Bs[OUTDIM];
    int tid = threadIdx.x;
    for (int i = tid; i < HID * OUTDIM; i += 128) Ws[i] = Wl[i];
    if (tid < OUTDIM) Bs[tid] = bl[tid];
    __syncthreads();

    int node = blockIdx.x * 128 + tid;
    if (node >= N) return;

    float acc[OUTDIM];
#pragma unroll
    for (int o = 0; o < OUTDIM; o++) acc[o] = Bs[o];

    const float4* h4 = (const float4*)(g_C + (size_t)node * HID);
#pragma unroll
    for (int c4 = 0; c4 < 16; c4++) {
        float4 v = h4[c4];
#pragma unroll
        for (int o = 0; o < OUTDIM; o++) {
            acc[o] = fmaf(v.x, Ws[(c4 * 4 + 0) * OUTDIM + o], acc[o]);
            acc[o] = fmaf(v.y, Ws[(c4 * 4 + 1) * OUTDIM + o], acc[o]);
            acc[o] = fmaf(v.z, Ws[(c4 * 4 + 2) * OUTDIM + o], acc[o]);
            acc[o] = fmaf(v.w, Ws[(c4 * 4 + 3) * OUTDIM + o], acc[o]);
        }
    }

    float m = acc[0];
#pragma unroll
    for (int o = 1; o < OUTDIM; o++) m = fmaxf(m, acc[o]);
    float s = 0.0f;
#pragma unroll
    for (int o = 0; o < OUTDIM; o++) s += expf(acc[o] - m);
    float lse = m + logf(s);
#pragma unroll
    for (int o = 0; o < OUTDIM; o++)
        out[(size_t)node * OUTDIM + o] = acc[o] - lse;
}

// ---------------------------------------------------------------------------
extern "C" void kernel_launch(void* const* d_in, const int* in_sizes, int n_in,
                              void* d_out, int out_size) {
    const float* x = (const float*)d_in[0];
    const int* ei = (const int*)d_in[1];   // int64 in reference -> int32 here
    const float* W1 = (const float*)d_in[2];
    const float* b1 = (const float*)d_in[3];
    const float* W2 = (const float*)d_in[4];
    const float* b2 = (const float*)d_in[5];
    const float* Wl = (const float*)d_in[6];
    const float* bl = (const float*)d_in[7];
    float* out = (float*)d_out;

    int N = in_sizes[0] / INDIM;
    int E = in_sizes[1] / 2;
    const int* row = ei;
    const int* col = ei + E;

    int nbE = (E + 255) / 256;
    int nbScan = (N + 1023) / 1024;

    constexpr int S1 = INDIM * 2 + 16;
    constexpr int S2 = HID * 2 + 16;
    constexpr int SMEM1 = 2 * (128 * S1) + 2 * (64 * S1);   // ~104.5 KB
    constexpr int SMEM2 = 2 * (128 * S2) + 2 * (64 * S2);   // ~55.3 KB
    cudaFuncSetAttribute(k_gemm_mma<INDIM, false>,
                         cudaFuncAttributeMaxDynamicSharedMemorySize, SMEM1);
    cudaFuncSetAttribute(k_gemm_mma<HID, true>,
                         cudaFuncAttributeMaxDynamicSharedMemorySize, SMEM2);

    // CSR build + normalization (g_deg zero on entry; scan1 re-zeroes it)
    k_deg<<<nbE, 256>>>(col, E);                                        // 1
    k_scan1<<<nbScan, 1024>>>(N);                                       // 2
    k_scan2<<<1, 128>>>(nbScan);                                        // 3

    // Layer 1
    k_gemm_mma<INDIM, false><<<(N + 127) / 128, 256, SMEM1>>>(x, W1, N); // 4
    k_fill<<<nbE, 256>>>(row, col, E);                                  // 5
    k_gather<<<(N * 32 + 255) / 256, 256>>>(b1, N);                     // 6

    // Layer 2
    k_gemm_mma<HID, true><<<(N + 127) / 128, 256, SMEM2>>>(x, W2, N);   // 7
    k_gather<<<(N * 32 + 255) / 256, 256>>>(b2, N);                     // 8

    // Head + log_softmax
    k_head<<<(N + 127) / 128, 128>>>(Wl, bl, out, N);                   // 9
}